// round 1
// baseline (speedup 1.0000x reference)
#include <cuda_runtime.h>
#include <math.h>

#define NN 256
#define MM 255
#define DD 256
#define FDELTA 0.1f

// Scratch (no cudaMalloc allowed)
__device__ float  g_z[NN * NN];
__device__ double g_acc;

// ---------------------------------------------------------------------------
// Kernel 1: pairwise L2 distances z[i][j] = ||f_i - f_j||
// feats(i,d) = features[((i&127)*2 + (i>>7))*256 + d]   (concat of the 2 views)
// 16x16 output tile per block, smem-staged, float4 inner loop.
// Also zeroes the global accumulator (block (0,0), ordered before main kernel).
// ---------------------------------------------------------------------------
__global__ void dist_kernel(const float* __restrict__ features) {
    __shared__ float A[16 * 264];   // 264-stride: 16B-aligned rows, bank-staggered
    __shared__ float B[16 * 264];

    const int bi  = blockIdx.y << 4;
    const int bj  = blockIdx.x << 4;
    const int tid = threadIdx.x;

    if (blockIdx.x == 0 && blockIdx.y == 0 && tid == 0) g_acc = 0.0;

    for (int idx = tid; idx < 16 * 256; idx += 256) {
        const int r = idx >> 8;
        const int c = idx & 255;
        const int gi = bi + r;
        const int gj = bj + r;
        A[r * 264 + c] = features[(((gi & 127) << 1) + (gi >> 7)) * 256 + c];
        B[r * 264 + c] = features[(((gj & 127) << 1) + (gj >> 7)) * 256 + c];
    }
    __syncthreads();

    const int ty = tid >> 4;
    const int tx = tid & 15;
    const float4* __restrict__ Ar = (const float4*)(A + ty * 264);
    const float4* __restrict__ Br = (const float4*)(B + tx * 264);

    float s = 0.0f;
#pragma unroll 8
    for (int d4 = 0; d4 < 64; d4++) {
        const float4 a = Ar[d4];
        const float4 b = Br[d4];
        const float dx = a.x - b.x, dy = a.y - b.y;
        const float dz = a.z - b.z, dw = a.w - b.w;
        s += dx * dx + dy * dy + dz * dz + dw * dw;
    }
    g_z[(bi + ty) * NN + (bj + tx)] = sqrtf(s);
}

// ---------------------------------------------------------------------------
// Kernel 2: one block per row i. Prologue builds per-row arrays (off-diagonal
// gather, sign, |label diff|, stable-sort ranks). Main loop: each thread owns
// one k and reduces over all j from smem (broadcast LDS).
//
//   d        = u_j - sgn_j * z_k        (u_j = sgn_j * z_j, precomputed)
//   pos (lad_j==lad_k, j!=k):  pos_acc += |d| * 2*sigmoid(|d| - delta)
//   neg (else, incl. j==k):    neg_acc += exp(-d) * 2*sigmoid((r_j-r_k)/delta - d)
//       with exp(-d) = E_j * (sgn_j>0 ? e^{z_k} : sgn_j<0 ? e^{-z_k} : 1)
//   term_k = pos_acc + log(neg_acc);  loss = sum(term)/(N*M)
// ---------------------------------------------------------------------------
__global__ void main_kernel(const int* __restrict__ labels) {
    __shared__ float4 sj[NN];   // {u_j, sgn_j, 10*rank_j, (float)lad_j}
    __shared__ float  sE[NN];   // exp(-u_j)
    __shared__ float  sZ[NN];   // z_j
    __shared__ int    slad[NN];
    __shared__ float  red[NN];

    const int i   = blockIdx.x;
    const int tid = threadIdx.x;
    const int li  = labels[i & 127];

    if (tid < MM) {
        const int c  = tid + (tid >= i);           // skip diagonal column
        const float z = g_z[i * NN + c];
        const int ld = li - labels[c & 127];
        const int lad = ld < 0 ? -ld : ld;
        const float sgn = (float)((ld > 0) - (ld < 0));
        slad[tid] = lad;
        sZ[tid]   = z;
        const float u = sgn * z;
        sj[tid].x = u;
        sj[tid].y = sgn;
        sj[tid].w = (float)lad;
        sE[tid]   = __expf(-u);
    }
    __syncthreads();

    if (tid < MM) {
        // stable rank: (# smaller) + (# equal with smaller index)
        const int ladk = slad[tid];
        int cnt = 0;
#pragma unroll 5
        for (int t = 0; t < MM; t++) {
            const int lt = slad[t];
            cnt += (lt < ladk) | ((lt == ladk) & (t < tid));
        }
        sj[tid].z = (float)cnt * 10.0f;            // rank / delta
    }
    __syncthreads();

    float term = 0.0f;
    if (tid < MM) {
        const float4 pk = sj[tid];
        const float zk   = sZ[tid];
        const float rk   = pk.z;
        const float ladk = pk.w;
        const float epk  = __expf(zk);
        const float enk  = __expf(-zk);

        float pos_acc = 0.0f;
        float neg_acc = 0.0f;
#pragma unroll 4
        for (int j = 0; j < MM; j++) {
            const float4 pj = sj[j];
            const float d = fmaf(-pj.y, zk, pj.x);             // u_j - sgn_j*zk
            if (pj.w == ladk && j != tid) {
                const float ad = fabsf(d);
                pos_acc += ad * __fdividef(2.0f, 1.0f + __expf(FDELTA - ad));
            } else {
                const float mult = (pj.y == 0.0f) ? 1.0f : (pj.y > 0.0f ? epk : enk);
                const float emd  = sE[j] * mult;               // exp(-d)
                const float mmd  = (pj.z - rk) - d;            // margin - d
                neg_acc += emd * __fdividef(2.0f, 1.0f + __expf(-mmd));
            }
        }
        term = pos_acc + logf(neg_acc);
    }
    red[tid] = term;
    __syncthreads();
#pragma unroll
    for (int s = 128; s > 0; s >>= 1) {
        if (tid < s) red[tid] += red[tid + s];
        __syncthreads();
    }
    if (tid == 0) atomicAdd(&g_acc, (double)red[0]);
}

__global__ void fin_kernel(float* __restrict__ out) {
    out[0] = (float)(g_acc / (double)(NN * MM));
}

extern "C" void kernel_launch(void* const* d_in, const int* in_sizes, int n_in,
                              void* d_out, int out_size) {
    const float* features = (const float*)d_in[0];   // [128,2,256] f32
    const int*   labels   = (const int*)d_in[1];     // [128,1] i32
    float*       out      = (float*)d_out;           // scalar f32

    dist_kernel<<<dim3(16, 16), 256>>>(features);
    main_kernel<<<NN, 256>>>(labels);
    fin_kernel<<<1, 1>>>(out);
}

// round 2
// speedup vs baseline: 1.4303x; 1.4303x over previous
#include <cuda_runtime.h>
#include <math.h>

#define NN 256
#define MM 255
#define FDELTA 0.1f

// Scratch (no cudaMalloc allowed)
__device__ float  g_zp[4][NN * NN];   // partial squared distances per 64-dim chunk
__device__ double g_acc;

// ---------------------------------------------------------------------------
// Kernel 1: partial squared distances. grid = 1024 blocks (16 x 16 tiles x 4
// K-chunks of 64 dims), 256 threads each, one output element per thread.
// Fully unrolled, float4, 4 accumulators -> batched LDS.128 + FMA ILP.
// ---------------------------------------------------------------------------
__global__ void distp_kernel(const float* __restrict__ features) {
    __shared__ float A[16 * 68];   // 68-float stride: 16B-aligned, low conflicts
    __shared__ float B[16 * 68];

    const int bid = blockIdx.x;
    const int bj  = (bid & 15) << 4;
    const int bi  = ((bid >> 4) & 15) << 4;
    const int bc  = bid >> 8;                 // K-chunk 0..3
    const int tid = threadIdx.x;

    if (bid == 0 && tid == 0) g_acc = 0.0;

    // Load 16 rows x 64 cols (as 16 float4) for A and B: one float4 each/thread
    {
        const int r   = tid >> 4;             // 0..15 row
        const int c4  = tid & 15;             // 0..15 float4 col
        const int gi  = bi + r;
        const int gj  = bj + r;
        const int col = (bc << 6) + (c4 << 2);
        const float4 a = *(const float4*)&features[(((gi & 127) << 1) + (gi >> 7)) * 256 + col];
        const float4 b = *(const float4*)&features[(((gj & 127) << 1) + (gj >> 7)) * 256 + col];
        *(float4*)&A[r * 68 + (c4 << 2)] = a;
        *(float4*)&B[r * 68 + (c4 << 2)] = b;
    }
    __syncthreads();

    const int ty = tid >> 4;
    const int tx = tid & 15;
    const float4* __restrict__ Ar = (const float4*)(A + ty * 68);
    const float4* __restrict__ Br = (const float4*)(B + tx * 68);

    float s0 = 0.0f, s1 = 0.0f, s2 = 0.0f, s3 = 0.0f;
#pragma unroll
    for (int q = 0; q < 16; q++) {
        const float4 a = Ar[q];
        const float4 b = Br[q];
        const float dx = a.x - b.x, dy = a.y - b.y;
        const float dz = a.z - b.z, dw = a.w - b.w;
        s0 += dx * dx; s1 += dy * dy; s2 += dz * dz; s3 += dw * dw;
    }
    g_zp[bc][(bi + ty) * NN + (bj + tx)] = (s0 + s1) + (s2 + s3);
}

// ---------------------------------------------------------------------------
// Kernel 2: one block per row i. Prologue: combine partial sq-dists -> z,
// build per-row arrays, stable ranks. Main loop: BRANCHLESS — both pos and
// neg terms computed every iter, combined with selects (no BSSY/BSYNC).
// j==k handled analytically: pterm(j==k)=0 exactly, its neg value is exactly
// 1.0 -> neg_acc initialized to 1 and the eq-lad mask routes j==k to pos(=0).
// ---------------------------------------------------------------------------
__global__ void main_kernel(const int* __restrict__ labels) {
    __shared__ float4 sj[NN];   // {u_j = sgn_j*z_j, sgn_j, 10*rank_j, (float)lad_j}
    __shared__ float  sE[NN];   // exp(-u_j)
    __shared__ float  sZ[NN];   // z_j
    __shared__ int    slad[NN];
    __shared__ float  red[NN];

    const int i   = blockIdx.x;
    const int tid = threadIdx.x;
    const int li  = labels[i & 127];

    if (tid < MM) {
        const int c  = tid + (tid >= i);       // skip diagonal column
        const int zi = i * NN + c;
        const float z = sqrtf((g_zp[0][zi] + g_zp[1][zi]) + (g_zp[2][zi] + g_zp[3][zi]));
        const int ld = li - labels[c & 127];
        const int lad = ld < 0 ? -ld : ld;
        const float sgn = (float)((ld > 0) - (ld < 0));
        slad[tid] = lad;
        sZ[tid]   = z;
        const float u = sgn * z;
        sj[tid].x = u;
        sj[tid].y = sgn;
        sj[tid].w = (float)lad;
        sE[tid]   = __expf(-u);
    }
    __syncthreads();

    if (tid < MM) {
        // stable rank: (# smaller) + (# equal with smaller index)
        const int ladk = slad[tid];
        int cnt = 0;
#pragma unroll 5
        for (int t = 0; t < MM; t++) {
            const int lt = slad[t];
            cnt += (lt < ladk) | ((lt == ladk) & (t < tid));
        }
        sj[tid].z = (float)cnt * 10.0f;        // rank / delta
    }
    __syncthreads();

    float term = 0.0f;
    if (tid < MM) {
        const float4 pk  = sj[tid];
        const float zk   = sZ[tid];
        const float rk   = pk.z;
        const float ladk = pk.w;
        const float epk  = __expf(zk);
        const float enk  = __expf(-zk);

        float pos_acc = 0.0f;
        float neg_acc = 1.0f;                  // j==k neg term, exactly 1
#pragma unroll 4
        for (int j = 0; j < MM; j++) {
            const float4 pj = sj[j];
            const float d  = fmaf(-pj.y, zk, pj.x);        // u_j - sgn_j*zk
            const float ad = fabsf(d);
            // pos weight: 2*sigmoid(ad - delta)
            const float sp = __expf(FDELTA - ad);
            const float wp = __fdividef(2.0f, 1.0f + sp);
            // neg: exp(-d) = E_j * exp(sgn_j * zk)  (selects, no exp in loop)
            const float mult = (pj.y == 0.0f) ? 1.0f : (pj.y > 0.0f ? epk : enk);
            const float emd  = sE[j] * mult;
            const float mmd  = (pj.z - rk) - d;            // margin - d
            const float sn = __expf(-mmd);
            const float wn = __fdividef(2.0f, 1.0f + sn);
            const bool eq = (pj.w == ladk);
            pos_acc += eq ? ad * wp  : 0.0f;
            neg_acc += eq ? 0.0f     : emd * wn;
        }
        term = pos_acc + logf(neg_acc);
    }
    red[tid] = term;
    __syncthreads();
#pragma unroll
    for (int s = 128; s > 0; s >>= 1) {
        if (tid < s) red[tid] += red[tid + s];
        __syncthreads();
    }
    if (tid == 0) atomicAdd(&g_acc, (double)red[0]);
}

__global__ void fin_kernel(float* __restrict__ out) {
    out[0] = (float)(g_acc / (double)(NN * MM));
}

extern "C" void kernel_launch(void* const* d_in, const int* in_sizes, int n_in,
                              void* d_out, int out_size) {
    const float* features = (const float*)d_in[0];   // [128,2,256] f32
    const int*   labels   = (const int*)d_in[1];     // [128,1] i32
    float*       out      = (float*)d_out;           // scalar f32

    distp_kernel<<<1024, 256>>>(features);
    main_kernel<<<NN, 256>>>(labels);
    fin_kernel<<<1, 1>>>(out);
}

// round 4
// speedup vs baseline: 2.0936x; 1.4638x over previous
#include <cuda_runtime.h>
#include <math.h>

#define NN 256
#define MM 255

// Scratch (no cudaMalloc allowed)
__device__ float  g_zp[8][NN * NN];   // partial squared distances per 32-dim chunk
__device__ double g_acc;

__device__ __forceinline__ float tanha(float x) {
    float y;
    asm("tanh.approx.f32 %0, %1;" : "=f"(y) : "f"(x));
    return y;
}

// ---------------------------------------------------------------------------
// Kernel 1: partial squared distances.
// 16(i) x 32(j) tile, K-chunk = 32 dims -> grid = 16 * 8 * 8 = 1024 blocks.
// Each thread produces TWO outputs sharing the A-row read (2x FMA per LDS).
// ---------------------------------------------------------------------------
__global__ void distp_kernel(const float* __restrict__ features) {
    __shared__ float A[16 * 36];
    __shared__ float B[32 * 36];

    const int bid = blockIdx.x;
    const int jt  = (bid & 7) << 5;          // j-tile base (32 wide)
    const int it  = ((bid >> 3) & 15) << 4;  // i-tile base (16 tall)
    const int ch  = bid >> 7;                // dim chunk 0..7 (32 dims)
    const int tid = threadIdx.x;

    if (bid == 0 && tid == 0) g_acc = 0.0;

    {
        const int r  = tid >> 3;             // 0..31
        const int c4 = tid & 7;              // 0..7 float4 within 32 dims
        const int col = (ch << 5) + (c4 << 2);
        if (tid < 128) {
            const int gi = it + r;
            const float4 a = *(const float4*)&features[(((gi & 127) << 1) + (gi >> 7)) * 256 + col];
            *(float4*)&A[r * 36 + (c4 << 2)] = a;
        }
        const int gj = jt + r;
        const float4 b = *(const float4*)&features[(((gj & 127) << 1) + (gj >> 7)) * 256 + col];
        *(float4*)&B[r * 36 + (c4 << 2)] = b;
    }
    __syncthreads();

    const int ty = tid >> 4;
    const int tx = tid & 15;
    const float4* __restrict__ Ar = (const float4*)(A + ty * 36);
    const float4* __restrict__ B0 = (const float4*)(B + tx * 36);
    const float4* __restrict__ B1 = (const float4*)(B + (tx + 16) * 36);

    float s0 = 0, s1 = 0, s2 = 0, s3 = 0;
    float t0 = 0, t1 = 0, t2 = 0, t3 = 0;
#pragma unroll
    for (int q = 0; q < 8; q++) {
        const float4 a = Ar[q];
        const float4 b = B0[q];
        const float4 c = B1[q];
        float d;
        d = a.x - b.x; s0 += d * d;  d = a.y - b.y; s1 += d * d;
        d = a.z - b.z; s2 += d * d;  d = a.w - b.w; s3 += d * d;
        d = a.x - c.x; t0 += d * d;  d = a.y - c.y; t1 += d * d;
        d = a.z - c.z; t2 += d * d;  d = a.w - c.w; t3 += d * d;
    }
    const int row = (it + ty) * NN + jt + tx;
    g_zp[ch][row]      = (s0 + s1) + (s2 + s3);
    g_zp[ch][row + 16] = (t0 + t1) + (t2 + t3);
}

// ---------------------------------------------------------------------------
// Kernel 2: 512 blocks (2 per row) x 128 threads. Prologue builds per-row
// arrays (z, sign, |lad|, stable ranks via histogram + vcmpeq4 tie count)
// and PARTITIONS the 255 j-records by sign into {+ | - | 0} segments.
// Main loop per k: three specialized segment loops, tanh-based sigmoids.
//   sgn=+1: d = u_j - zk, exp(-d) = E_j * e^{zk}
//   sgn=-1: d = u_j + zk, exp(-d) = E_j * e^{-zk}
//   sgn= 0: d = 0 exactly -> contributes (1 + tanh(rh_j - rh_k)) to neg
//           iff ladk != 0 (else it is a pos pair contributing exactly 0)
// j==k: lands in its sign segment with d = 0 -> pos += 0; its true neg
// contribution is exactly 1 -> neg_acc initialized to 1.
// ---------------------------------------------------------------------------
__global__ void main_kernel(const int* __restrict__ labels) {
    __shared__ float4 sj4[NN];              // permuted {u, E, rh, ladf}
    __shared__ float  sZ[NN], sRH[NN], sLADF[NN];
    __shared__ unsigned char slad8[NN];
    __shared__ int    hist[16];             // lad histogram -> prefix (in place)
    __shared__ int    segcnt[4];
    __shared__ float  red[128];

    const int bid  = blockIdx.x;
    const int i    = bid >> 1;
    const int half = bid & 1;
    const int tid  = threadIdx.x;
    const int li   = labels[i & 127];

    if (tid < 16) hist[tid] = 0;
    if (tid < 4)  segcnt[tid] = 0;
    if (tid == 0) slad8[255] = 0xFF;        // sentinel: never < or == any lad
    __syncthreads();

    // ---- phase 1: per-j basics (each thread owns j = tid and tid+128) ----
    float zj[2], sgnv[2];
    int   ladv[2];
#pragma unroll
    for (int q = 0; q < 2; q++) {
        const int j = tid + (q << 7);
        if (j < MM) {
            const int c  = j + (j >= i);
            const int zi = i * NN + c;
            float s = 0.0f;
#pragma unroll
            for (int ch = 0; ch < 8; ch++) s += g_zp[ch][zi];
            const float z = sqrtf(s);
            const int ld  = li - labels[c & 127];
            const int lad = ld < 0 ? -ld : ld;
            zj[q]   = z;
            ladv[q] = lad;
            sgnv[q] = (float)((ld > 0) - (ld < 0));
            slad8[j] = (unsigned char)lad;
            sZ[j]    = z;
            sLADF[j] = (float)lad;
            atomicAdd(&hist[lad], 1);
        }
    }
    __syncthreads();

    if (tid == 0) {                          // exclusive prefix over 16 bins
        int run = 0;
#pragma unroll
        for (int b = 0; b < 16; b++) { const int h = hist[b]; hist[b] = run; run += h; }
    }
    __syncthreads();

    // ---- phase 2: stable ranks (tie via vcmpeq4) + segment ordinals ----
    const unsigned int* __restrict__ w32 = (const unsigned int*)slad8;
    int   slot[2], segv[2];
    float rhv[2], uv[2], Ev[2];
#pragma unroll
    for (int q = 0; q < 2; q++) {
        const int j = tid + (q << 7);
        if (j < MM) {
            const int lad = ladv[q];
            const unsigned int splat = (unsigned int)lad * 0x01010101u;
            int tie = 0;
            const int wb = j >> 2;
            for (int w = 0; w < wb; w++)
                tie += __popc(__vcmpeq4(w32[w], splat)) >> 3;
            const int rem = j & 3;
            if (rem) {
                const unsigned int pmask = (1u << (rem << 3)) - 1u;
                tie += __popc(__vcmpeq4(w32[wb], splat) & pmask) >> 3;
            }
            const int rank = hist[lad] + tie;
            const float rh = 5.0f * (float)rank;   // (rank/delta)/2 = 5*rank
            rhv[q] = rh;
            sRH[j] = rh;
            const float sgn = sgnv[q];
            const float u   = sgn * zj[q];
            uv[q] = u;
            Ev[q] = __expf(-u);
            const int seg = sgn > 0.0f ? 0 : (sgn < 0.0f ? 1 : 2);
            segv[q] = seg;
            slot[q] = atomicAdd(&segcnt[seg], 1);
        }
    }
    __syncthreads();

    const int n0 = segcnt[0];               // [0,n0): sgn=+1
    const int n1 = n0 + segcnt[1];          // [n0,n1): sgn=-1 ; [n1,255): sgn=0
#pragma unroll
    for (int q = 0; q < 2; q++) {
        const int j = tid + (q << 7);
        if (j < MM) {
            const int base = segv[q] == 0 ? 0 : (segv[q] == 1 ? n0 : n1);
            sj4[base + slot[q]] = make_float4(uv[q], Ev[q], rhv[q], (float)ladv[q]);
        }
    }
    __syncthreads();

    // ---- main loop: k = half*128 + tid ----
    float term = 0.0f;
    const int k = (half << 7) + tid;
    if (k < MM) {
        const float zk   = sZ[k];
        const float rhk  = sRH[k];
        const float ladk = sLADF[k];
        const float epk  = __expf(zk);
        const float enk  = __expf(-zk);

        float pos = 0.0f;
        float neg = 1.0f;                   // exact j==k neg contribution

#pragma unroll 4
        for (int j = 0; j < n0; j++) {      // sgn = +1
            const float4 p = sj4[j];
            const float d  = p.x - zk;
            const float ad = fabsf(d);
            const float tp = tanha(fmaf(0.5f, ad, -0.05f));
            const float pterm = fmaf(ad, tp, ad);
            const float emd = p.y * epk;
            const float tn  = tanha((p.z - rhk) - 0.5f * d);
            const float nterm = fmaf(emd, tn, emd);
            const bool eq = (p.w == ladk);
            pos += eq ? pterm : 0.0f;
            neg += eq ? 0.0f  : nterm;
        }
#pragma unroll 4
        for (int j = n0; j < n1; j++) {     // sgn = -1
            const float4 p = sj4[j];
            const float d  = p.x + zk;
            const float ad = fabsf(d);
            const float tp = tanha(fmaf(0.5f, ad, -0.05f));
            const float pterm = fmaf(ad, tp, ad);
            const float emd = p.y * enk;
            const float tn  = tanha((p.z - rhk) - 0.5f * d);
            const float nterm = fmaf(emd, tn, emd);
            const bool eq = (p.w == ladk);
            pos += eq ? pterm : 0.0f;
            neg += eq ? 0.0f  : nterm;
        }
        if (ladk != 0.0f) {                 // sgn = 0 segment, d == 0 exactly
#pragma unroll 4
            for (int j = n1; j < MM; j++) {
                const float tn = tanha(sj4[j].z - rhk);
                neg += 1.0f + tn;
            }
        }
        term = pos + logf(neg);
    }
    red[tid] = term;
    __syncthreads();
#pragma unroll
    for (int s = 64; s > 0; s >>= 1) {
        if (tid < s) red[tid] += red[tid + s];
        __syncthreads();
    }
    if (tid == 0) atomicAdd(&g_acc, (double)red[0]);
}

__global__ void fin_kernel(float* __restrict__ out) {
    out[0] = (float)(g_acc / (double)(NN * MM));
}

extern "C" void kernel_launch(void* const* d_in, const int* in_sizes, int n_in,
                              void* d_out, int out_size) {
    const float* features = (const float*)d_in[0];   // [128,2,256] f32
    const int*   labels   = (const int*)d_in[1];     // [128,1] i32
    float*       out      = (float*)d_out;           // scalar f32

    distp_kernel<<<1024, 256>>>(features);
    main_kernel<<<512, 128>>>(labels);
    fin_kernel<<<1, 1>>>(out);
}

// round 5
// speedup vs baseline: 2.2545x; 1.0768x over previous
#include <cuda_runtime.h>
#include <math.h>

#define NN 256
#define MM 255

// Scratch (no cudaMalloc allowed)
__device__ float  g_gp[8][NN * NN];   // partial Gram per 32-dim chunk
__device__ double g_acc;

__device__ __forceinline__ float tanha(float x) {
    float y;
    asm("tanh.approx.f32 %0, %1;" : "=f"(y) : "f"(x));
    return y;
}

// ---------------------------------------------------------------------------
// Kernel 1: partial Gram matrix G_ij = sum_d f_i[d] f_j[d] over a 32-dim chunk.
// 32x32 tile, 2x2 register tiling, K-major smem (1 FMA per element-pair).
// grid = 8(i) x 8(j) x 8(chunk) = 512 blocks, 256 threads.
// Norms are diag(G); distances derived in main: z^2 = Gii + Gjj - 2 Gij.
// ---------------------------------------------------------------------------
__global__ void gram_kernel(const float* __restrict__ features) {
    __shared__ float As[32 * 34];   // K-major: As[k*34 + row], pad 34 (8B-aligned float2)
    __shared__ float Bs[32 * 34];

    const int bid = blockIdx.x;
    const int jt  = (bid & 7) << 5;
    const int it  = ((bid >> 3) & 7) << 5;
    const int ch  = bid >> 6;               // 0..7
    const int tid = threadIdx.x;

    if (bid == 0 && tid == 0) g_acc = 0.0;

    {   // load 32 rows x 32 dims, transpose into K-major smem
        const int r   = tid >> 3;           // 0..31 row
        const int c4  = tid & 7;            // 0..7 float4 within chunk
        const int col = (ch << 5) + (c4 << 2);
        const int gi  = it + r;
        const int gj  = jt + r;
        const float4 a = *(const float4*)&features[(((gi & 127) << 1) + (gi >> 7)) * 256 + col];
        const float4 b = *(const float4*)&features[(((gj & 127) << 1) + (gj >> 7)) * 256 + col];
        const int k0 = c4 << 2;
        As[(k0 + 0) * 34 + r] = a.x;  As[(k0 + 1) * 34 + r] = a.y;
        As[(k0 + 2) * 34 + r] = a.z;  As[(k0 + 3) * 34 + r] = a.w;
        Bs[(k0 + 0) * 34 + r] = b.x;  Bs[(k0 + 1) * 34 + r] = b.y;
        Bs[(k0 + 2) * 34 + r] = b.z;  Bs[(k0 + 3) * 34 + r] = b.w;
    }
    __syncthreads();

    const int ty = tid >> 4;                // 0..15 -> rows 2ty,2ty+1
    const int tx = tid & 15;                // 0..15 -> cols 2tx,2tx+1
    float a00 = 0, a01 = 0, a10 = 0, a11 = 0;
#pragma unroll
    for (int k = 0; k < 32; k++) {
        const float2 a = *(const float2*)&As[k * 34 + (ty << 1)];
        const float2 b = *(const float2*)&Bs[k * 34 + (tx << 1)];
        a00 = fmaf(a.x, b.x, a00);
        a01 = fmaf(a.x, b.y, a01);
        a10 = fmaf(a.y, b.x, a10);
        a11 = fmaf(a.y, b.y, a11);
    }
    const int r0 = it + (ty << 1);
    const int c0 = jt + (tx << 1);
    *(float2*)&g_gp[ch][r0 * NN + c0]       = make_float2(a00, a01);
    *(float2*)&g_gp[ch][(r0 + 1) * NN + c0] = make_float2(a10, a11);
}

// ---------------------------------------------------------------------------
// Kernel 2: 512 blocks (2 per row i) x 128 threads.
// Prologue: z from Gram partials; lads/signs; stable ranks via match_any
// group counting; place j-records into segments [+ by lad | - by lad | zero],
// giving contiguous equal-lad runs. Main loop per permuted k:
//   neg over +/- segments SKIPPING the eq run:  emd = E_j * e^{+-zk};
//       tn = tanh(q_j - ck);  neg += emd*(1+tn)   (q_j = rh_j - u_j/2)
//   zero segment (if ladk!=0): neg += 1 + tanh(rh_j - rhk)
//   eq-run fixup (pos pairs): pos += ad*(1+tanh(ad/2 - 0.05)), ad = |u_j -+ zk|
//   j==k excluded by the eq skip; its exact neg value 1 -> neg init = 1.
// ---------------------------------------------------------------------------
__global__ void main_kernel(const int* __restrict__ labels) {
    __shared__ float2 sEQ[NN];     // permuted {E_j, q_j}
    __shared__ float4 sKR[NN];     // permuted {z, rh, ladf, 0}
    __shared__ float  sU[NN];      // permuted u_j
    __shared__ int    cntL[8][16]; // per (group, lad) counts
    __shared__ int    cntK[8][32]; // per (group, key) counts
    __shared__ int    sumL[16], sumK[32];
    __shared__ int    histBase[16];
    __shared__ int    BP[10], CP[10], BM[10], CM[10];
    __shared__ int    sNP, sNE;
    __shared__ float  red[128];

    const int bid  = blockIdx.x;
    const int i    = bid >> 1;
    const int half = bid & 1;
    const int tid  = threadIdx.x;
    const int lane = tid & 31;
    const int wid  = tid >> 5;
    const unsigned lt = (1u << lane) - 1u;
    const int li   = labels[i & 127];

    if (tid < 128) { cntL[tid >> 4][tid & 15] = 0; cntK[tid >> 5][tid & 31] = 0;
                     cntK[4 + (tid >> 5)][tid & 31] = 0; }
    __syncthreads();

    float Gii = 0.0f;
#pragma unroll
    for (int ch = 0; ch < 8; ch++) Gii += g_gp[ch][i * NN + i];

    // ---- phase 1: per-j basics + warp match counting ----
    float zj[2], sgnv[2];
    int   ladv[2], keyv[2], tieL[2], tieK[2];
#pragma unroll
    for (int q = 0; q < 2; q++) {
        const int j = tid + (q << 7);
        const bool valid = (j < MM);
        int lad = 15, key = 31;
        if (valid) {
            const int c = j + (j >= i);
            float gij = 0.0f, gjj = 0.0f;
#pragma unroll
            for (int ch = 0; ch < 8; ch++) {
                gij += g_gp[ch][i * NN + c];
                gjj += g_gp[ch][c * NN + c];
            }
            const float z = sqrtf(fmaxf(fmaf(-2.0f, gij, Gii + gjj), 0.0f));
            const int ld  = li - labels[c & 127];
            lad = ld < 0 ? -ld : ld;
            key = (lad == 0) ? 0 : (ld > 0 ? lad : 16 + lad);
            zj[q]   = z;
            sgnv[q] = (float)((ld > 0) - (ld < 0));
        }
        ladv[q] = lad;
        keyv[q] = key;
        const unsigned mL = __match_any_sync(0xFFFFFFFFu, lad);
        const unsigned mK = __match_any_sync(0xFFFFFFFFu, key);
        tieL[q] = __popc(mL & lt);
        tieK[q] = __popc(mK & lt);
        const int g = (q << 2) | wid;
        cntL[g][lad & 15] = __popc(mL);
        cntK[g][key]      = __popc(mK);
    }
    __syncthreads();

    if (tid < 16) { int s = 0;
#pragma unroll
        for (int g = 0; g < 8; g++) s += cntL[g][tid];
        sumL[tid] = s; }
    if (tid < 32) { int s = 0;
#pragma unroll
        for (int g = 0; g < 8; g++) s += cntK[g][tid];
        sumK[tid] = s; }
    __syncthreads();

    if (tid == 0) {
        int run = 0;
#pragma unroll
        for (int b = 0; b < 16; b++) { histBase[b] = run; run += sumL[b]; }
        run = 0;
#pragma unroll
        for (int b = 1; b <= 9; b++) { BP[b] = run; CP[b] = sumK[b]; run += sumK[b]; }
        sNP = run;
#pragma unroll
        for (int b = 1; b <= 9; b++) { BM[b] = run; CM[b] = sumK[16 + b]; run += sumK[16 + b]; }
        sNE = run;
        BP[0] = 0; CP[0] = 0; BM[0] = sNP; CM[0] = 0;
    }
    __syncthreads();

    // ---- phase 2: ranks + deterministic placement ----
#pragma unroll
    for (int q = 0; q < 2; q++) {
        const int j = tid + (q << 7);
        if (j < MM) {
            const int lad = ladv[q], key = keyv[q];
            const int g = (q << 2) | wid;
            int tl = tieL[q], tk = tieK[q];
            for (int gg = 0; gg < g; gg++) { tl += cntL[gg][lad]; tk += cntK[gg][key]; }
            const int rank = histBase[lad] + tl;
            const float rh = 5.0f * (float)rank;     // (rank/delta)/2
            int place;
            if (key == 0)       place = sNE + tk;
            else if (key < 16)  place = BP[key] + tk;
            else                place = BM[key - 16] + tk;
            const float u = sgnv[q] * zj[q];
            const float E = __expf(-u);
            const float qv = fmaf(-0.5f, u, rh);
            sEQ[place] = make_float2(E, qv);
            sKR[place] = make_float4(zj[q], rh, (float)lad, 0.0f);
            sU[place]  = u;
        }
    }
    __syncthreads();

    // ---- main loop: thread handles permuted k index p ----
    float term = 0.0f;
    const int p = (half << 7) + tid;
    if (p < MM) {
        const float4 kr = sKR[p];
        const float zk  = kr.x;
        const float rhk = kr.y;
        const int ladk  = (int)kr.z;
        const float epk = __expf(zk);
        const float enk = __expf(-zk);
        const float ckP = fmaf(-0.5f, zk, rhk);
        const float ckM = fmaf( 0.5f, zk, rhk);
        const int NP = sNP, NE = sNE;
        const int loP = BP[ladk], hiP = loP + CP[ladk];
        const int loM = BM[ladk], hiM = loM + CM[ladk];

        float neg = 1.0f;                   // exact j==k contribution
        float pos = 0.0f;

#pragma unroll 4
        for (int j = 0; j < loP; j++) {     // + seg before eq run
            const float2 t = sEQ[j];
            const float emd = t.x * epk;
            const float tn  = tanha(t.y - ckP);
            neg += fmaf(emd, tn, emd);
        }
#pragma unroll 4
        for (int j = hiP; j < NP; j++) {    // + seg after eq run
            const float2 t = sEQ[j];
            const float emd = t.x * epk;
            const float tn  = tanha(t.y - ckP);
            neg += fmaf(emd, tn, emd);
        }
#pragma unroll 4
        for (int j = loM; j > NP; ) {       // dummy guard transform avoided; use standard
            j = NP; break;
        }
#pragma unroll 4
        for (int j = NP; j < loM; j++) {    // - seg before eq run
            const float2 t = sEQ[j];
            const float emd = t.x * enk;
            const float tn  = tanha(t.y - ckM);
            neg += fmaf(emd, tn, emd);
        }
#pragma unroll 4
        for (int j = hiM; j < NE; j++) {    // - seg after eq run
            const float2 t = sEQ[j];
            const float emd = t.x * enk;
            const float tn  = tanha(t.y - ckM);
            neg += fmaf(emd, tn, emd);
        }
        if (ladk != 0) {
#pragma unroll 4
            for (int j = NE; j < MM; j++) { // zero seg: d == 0 exactly
                const float tn = tanha(sEQ[j].y - rhk);
                neg += 1.0f + tn;
            }
            for (int j = loP; j < hiP; j++) {  // pos fixup (+)
                const float d  = sU[j] - zk;
                const float ad = fabsf(d);
                const float tp = tanha(fmaf(0.5f, ad, -0.05f));
                pos += fmaf(ad, tp, ad);
            }
            for (int j = loM; j < hiM; j++) {  // pos fixup (-)
                const float d  = sU[j] + zk;
                const float ad = fabsf(d);
                const float tp = tanha(fmaf(0.5f, ad, -0.05f));
                pos += fmaf(ad, tp, ad);
            }
        }
        term = pos + logf(neg);
    }
    red[tid] = term;
    __syncthreads();
#pragma unroll
    for (int s = 64; s > 0; s >>= 1) {
        if (tid < s) red[tid] += red[tid + s];
        __syncthreads();
    }
    if (tid == 0) atomicAdd(&g_acc, (double)red[0]);
}

__global__ void fin_kernel(float* __restrict__ out) {
    out[0] = (float)(g_acc / (double)(NN * MM));
}

extern "C" void kernel_launch(void* const* d_in, const int* in_sizes, int n_in,
                              void* d_out, int out_size) {
    const float* features = (const float*)d_in[0];   // [128,2,256] f32
    const int*   labels   = (const int*)d_in[1];     // [128,1] i32
    float*       out      = (float*)d_out;           // scalar f32

    gram_kernel<<<512, 256>>>(features);
    main_kernel<<<512, 128>>>(labels);
    fin_kernel<<<1, 1>>>(out);
}